// round 4
// baseline (speedup 1.0000x reference)
#include <cuda_runtime.h>
#include <math.h>

// ---------------------------------------------------------------------------
// LabelSmoothing KL-div loss:
//   total = sum_valid_rows [ C - eps*(rowsum - p0 - p_tgt) - 0.9*p_tgt ]
// Split as:  (-eps) * [flat weighted sum of all elements of valid rows]
//          +  per-row correction  C + eps*p0 - (0.9-eps)*p_tgt.
// Persistent fat blocks: 2 CTAs/SM x 1024 threads, all resident, each block
// streams whole rows (fewer, fatter HBM streams). No per-row syncs.
// Corrections + final reduce done once in the last-finishing block.
// ---------------------------------------------------------------------------

#define PAD_IDX 0

__device__ double       g_partials[4096];    // per-block flat partials
__device__ unsigned int g_count = 0;         // self-resetting

__global__ __launch_bounds__(1024, 2) void ls_kernel(
    const float* __restrict__ pred,
    const void*  __restrict__ tgt_raw,
    float* __restrict__ out,
    int N, int V, double eps, double coefC, double w_tgt)
{
    const int tid = threadIdx.x;
    const int wid = tid >> 5;
    const int lid = tid & 31;
    const int bd  = (int)blockDim.x;     // 1024
    const int G   = (int)gridDim.x;

    __shared__ float        warpsum[32];
    __shared__ int          sh_is64;
    __shared__ unsigned int sh_islast;

    // ---- dtype detection (warp 0): odd int32 words of [0,64) all zero
    //      <=> little-endian int64 layout. Safe to read under both layouts. ----
    if (wid == 0) {
        int idx = 2 * lid + 1;
        int v = (idx < N) ? ((const int*)tgt_raw)[idx] : 0;
        unsigned int nz = __ballot_sync(0xffffffffu, v != 0);
        if (lid == 0) sh_is64 = (nz == 0u) ? 1 : 0;
    }
    __syncthreads();
    const int is64 = sh_is64;

    const int nv4 = V >> 2;

    // ---- persistent row loop: weighted flat sum, no per-row reduction ----
    float acc = 0.0f;
    for (int r = blockIdx.x; r < N; r += G) {
        long long t;
        if (is64) t = ((const long long*)tgt_raw)[r];
        else      t = (long long)((const int*)tgt_raw)[r];
        const float w = (t != PAD_IDX) ? 1.0f : 0.0f;

        const float4* __restrict__ p4 =
            (const float4*)(pred + (size_t)r * (size_t)V);

        float a0 = 0.0f, a1 = 0.0f, a2 = 0.0f, a3 = 0.0f;
        int i = tid;
        for (; i + 3 * bd < nv4; i += 4 * bd) {
            float4 v0 = __ldcs(p4 + i);
            float4 v1 = __ldcs(p4 + i + bd);
            float4 v2 = __ldcs(p4 + i + 2 * bd);
            float4 v3 = __ldcs(p4 + i + 3 * bd);
            a0 += (v0.x + v0.y) + (v0.z + v0.w);
            a1 += (v1.x + v1.y) + (v1.z + v1.w);
            a2 += (v2.x + v2.y) + (v2.z + v2.w);
            a3 += (v3.x + v3.y) + (v3.z + v3.w);
        }
        #pragma unroll 4
        for (; i < nv4; i += bd) {
            float4 v = __ldcs(p4 + i);
            a0 += (v.x + v.y) + (v.z + v.w);
        }
        // scalar tail (V % 4 != 0; not hit for V=32000 but keep general)
        for (int j = (nv4 << 2) + tid; j < V; j += bd)
            a0 += __ldcs(((const float*)p4) + j);

        acc += w * ((a0 + a1) + (a2 + a3));
    }

    // ---- one block reduction, ever ----
    float local = acc;
    #pragma unroll
    for (int o = 16; o > 0; o >>= 1)
        local += __shfl_xor_sync(0xffffffffu, local, o);
    if (lid == 0) warpsum[wid] = local;
    __syncthreads();
    if (wid == 0) {
        float s = (lid < (bd >> 5)) ? warpsum[lid] : 0.0f;
        #pragma unroll
        for (int o = 16; o > 0; o >>= 1)
            s += __shfl_xor_sync(0xffffffffu, s, o);
        if (lid == 0) {
            g_partials[blockIdx.x] = (double)s;
            __threadfence();
            unsigned int done = atomicAdd(&g_count, 1u);
            sh_islast = (done == (unsigned int)(G - 1)) ? 1u : 0u;
        }
    }
    __syncthreads();

    // ---- last block: per-row corrections + final deterministic reduction ----
    if (sh_islast) {
        __shared__ double ws[32];
        double dl = 0.0;

        // corrections: C + eps*p0 - (0.9-eps)*p_tgt for each valid row
        for (int r = tid; r < N; r += bd) {
            long long t;
            if (is64) t = ((const long long*)tgt_raw)[r];
            else      t = (long long)((const int*)tgt_raw)[r];
            if (t != PAD_IDX && t >= 0 && t < (long long)V) {
                const float* pr = pred + (size_t)r * (size_t)V;
                double p0   = (double)__ldg(&pr[0]);
                double ptgt = (double)__ldg(&pr[t]);
                dl += coefC + eps * p0 - w_tgt * ptgt;
            }
        }
        // fold in (-eps) * block partials
        for (int k = tid; k < G; k += bd)
            dl += (-eps) * g_partials[k];

        #pragma unroll
        for (int o = 16; o > 0; o >>= 1)
            dl += __shfl_xor_sync(0xffffffffu, dl, o);
        if (lid == 0) ws[wid] = dl;
        __syncthreads();
        if (wid == 0) {
            double s = (lid < (bd >> 5)) ? ws[lid] : 0.0;
            #pragma unroll
            for (int o = 16; o > 0; o >>= 1)
                s += __shfl_xor_sync(0xffffffffu, s, o);
            if (lid == 0) {
                out[0] = (float)s;
                g_count = 0;   // reset for next graph replay
            }
        }
    }
}

extern "C" void kernel_launch(void* const* d_in, const int* in_sizes, int n_in,
                              void* d_out, int out_size)
{
    const float* pred = (const float*)d_in[0];
    const void*  tgt  = d_in[1];

    const int total = in_sizes[0];   // B*S*V
    const int N     = in_sizes[1];   // B*S rows
    const int V     = total / N;

    const double smoothing = 0.1;
    const double eps   = smoothing / (double)(V - 2);
    const double coefC = (double)(V - 2) * eps * log(eps)
                       + (1.0 - smoothing) * log(1.0 - smoothing);
    const double w_tgt = (1.0 - smoothing) - eps;

    int nsm = 148;
    cudaDeviceGetAttribute(&nsm, cudaDevAttrMultiProcessorCount, 0);
    int G = 2 * nsm;                 // 2 CTAs/SM, all resident
    if (G > 4096) G = 4096;

    ls_kernel<<<G, 1024>>>(pred, tgt, (float*)d_out, N, V, eps, coefC, w_tgt);
}